// round 3
// baseline (speedup 1.0000x reference)
#include <cuda_runtime.h>
#include <cuda_bf16.h>

#define N_NODES 10000
#define DDIM    128
#define NSAMP   8
#define NQUERY  65536

__global__ __launch_bounds__(256)
void madgraph_kernel(const int* __restrict__ src,
                     const int* __restrict__ dst,
                     const int* __restrict__ mid0,
                     const int* __restrict__ mid1,
                     const float* __restrict__ position,
                     const float* __restrict__ src_field,
                     const float* __restrict__ dst_field,
                     const float* __restrict__ unc,
                     const float* __restrict__ edge,
                     float* __restrict__ out)
{
    const int warp = (blockIdx.x * blockDim.x + threadIdx.x) >> 5;
    const int lane = threadIdx.x & 31;
    if (warp >= NQUERY) return;
    const int n = warp;

    const int s_node = __ldg(&src[n]);
    const int d_node = __ldg(&dst[n]);

    const float4* pos4 = (const float4*)position;
    const float4* sf4  = (const float4*)src_field;
    const float4* df4  = (const float4*)dst_field;

    // Each lane owns float4 slice [lane*4 .. lane*4+3] of a 128-dim row.
    const float4 ps = __ldg(&pos4[s_node * 32 + lane]);
    const float4 pd = __ldg(&pos4[d_node * 32 + lane]);
    const float4 fd = __ldg(&df4 [d_node * 32 + lane]);
    const float4 fs = __ldg(&sf4 [s_node * 32 + lane]);

    // Lane l<8 holds mid0[n][l]; lanes 8..15 hold mid1[n][l-8]; broadcast per sample.
    int m_own = 0;
    if (lane < 8)        m_own = __ldg(&mid0[n * 8 + lane]);
    else if (lane < 16)  m_own = __ldg(&mid1[n * 8 + (lane - 8)]);

    float mydot = 0.f, mydist2 = 0.f;

    #pragma unroll
    for (int s = 0; s < 16; ++s) {
        const int m = __shfl_sync(0xFFFFFFFFu, m_own, s);
        const float4 pm = __ldg(&pos4[m * 32 + lane]);
        const float4 base = (s < 8) ? ps : pd;
        const float4 f    = (s < 8) ? fd : fs;
        float4 dv;
        dv.x = base.x - pm.x;
        dv.y = base.y - pm.y;
        dv.z = base.z - pm.z;
        dv.w = base.w - pm.w;
        float pdot = dv.x * f.x + dv.y * f.y + dv.z * f.z + dv.w * f.w;
        float pn2  = dv.x * dv.x + dv.y * dv.y + dv.z * dv.z + dv.w * dv.w;
        #pragma unroll
        for (int o = 16; o > 0; o >>= 1) {
            pdot += __shfl_xor_sync(0xFFFFFFFFu, pdot, o);
            pn2  += __shfl_xor_sync(0xFFFFFFFFu, pn2,  o);
        }
        if (lane == s) { mydot = pdot; mydist2 = pn2; }
    }

    const float u = __ldg(unc);

    // Lanes 0..15: one softmax slot each. Others neutralized for the reduces.
    float a, logit;
    if (lane < 16) {
        int eidx;
        if (lane < 8) eidx = m_own * N_NODES + d_node;   // edge[mid0[s], dst]
        else          eidx = s_node * N_NODES + m_own;   // edge[src, mid1[s]]
        const float ev = __ldg(&edge[eidx]);
        logit = mydot + u * ev;
        a = 1.0f - sqrtf(mydist2);
    } else {
        logit = 0.f;
        a = -1e30f;
    }

    // max over the 16 valid lanes (others are -1e30)
    float mx = a;
    #pragma unroll
    for (int o = 16; o > 0; o >>= 1)
        mx = fmaxf(mx, __shfl_xor_sync(0xFFFFFFFFu, mx, o));

    const float e   = (lane < 16) ? __expf(a - mx) : 0.f;
    float num = logit * e;
    float den = e;
    #pragma unroll
    for (int o = 16; o > 0; o >>= 1) {
        num += __shfl_xor_sync(0xFFFFFFFFu, num, o);
        den += __shfl_xor_sync(0xFFFFFFFFu, den, o);
    }

    if (lane == 0) out[n] = num / den;
}

extern "C" void kernel_launch(void* const* d_in, const int* in_sizes, int n_in,
                              void* d_out, int out_size)
{
    const int*   src      = (const int*)  d_in[0];
    const int*   dst      = (const int*)  d_in[1];
    const int*   mid0     = (const int*)  d_in[2];
    const int*   mid1     = (const int*)  d_in[3];
    const float* position = (const float*)d_in[4];
    const float* src_f    = (const float*)d_in[5];
    const float* dst_f    = (const float*)d_in[6];
    const float* unc      = (const float*)d_in[7];
    const float* edge     = (const float*)d_in[8];
    float*       out      = (float*)      d_out;

    // 8 warps (8 queries) per 256-thread block
    const int blocks = NQUERY / 8;
    madgraph_kernel<<<blocks, 256>>>(src, dst, mid0, mid1, position,
                                     src_f, dst_f, unc, edge, out);
}

// round 4
// speedup vs baseline: 1.0117x; 1.0117x over previous
#include <cuda_runtime.h>
#include <cuda_bf16.h>

#define N_NODES 10000
#define DDIM    128
#define NSAMP   8
#define NQUERY  65536

__global__ __launch_bounds__(256)
void madgraph_kernel(const int* __restrict__ src,
                     const int* __restrict__ dst,
                     const int* __restrict__ mid0,
                     const int* __restrict__ mid1,
                     const float* __restrict__ position,
                     const float* __restrict__ src_field,
                     const float* __restrict__ dst_field,
                     const float* __restrict__ unc,
                     const float* __restrict__ edge,
                     float* __restrict__ out)
{
    const int warp = (blockIdx.x * blockDim.x + threadIdx.x) >> 5;
    const int lane = threadIdx.x & 31;
    if (warp >= NQUERY) return;
    const int n = warp;

    const int s_node = __ldg(&src[n]);
    const int d_node = __ldg(&dst[n]);

    const float4* pos4 = (const float4*)position;
    const float4* sf4  = (const float4*)src_field;
    const float4* df4  = (const float4*)dst_field;

    // Each lane owns float4 slice [lane*4 .. lane*4+3] of a 128-dim row.
    const float4 ps = __ldg(&pos4[s_node * 32 + lane]);
    const float4 pd = __ldg(&pos4[d_node * 32 + lane]);
    const float4 fd = __ldg(&df4 [d_node * 32 + lane]);
    const float4 fs = __ldg(&sf4 [s_node * 32 + lane]);

    // Lane l<8 holds mid0[n][l]; lanes 8..15 hold mid1[n][l-8]; broadcast per sample.
    int m_own = 0;
    if (lane < 8)        m_own = __ldg(&mid0[n * 8 + lane]);
    else if (lane < 16)  m_own = __ldg(&mid1[n * 8 + (lane - 8)]);

    float mydot = 0.f, mydist2 = 0.f;

    #pragma unroll
    for (int s = 0; s < 16; ++s) {
        const int m = __shfl_sync(0xFFFFFFFFu, m_own, s);
        const float4 pm = __ldg(&pos4[m * 32 + lane]);
        const float4 base = (s < 8) ? ps : pd;
        const float4 f    = (s < 8) ? fd : fs;
        float4 dv;
        dv.x = base.x - pm.x;
        dv.y = base.y - pm.y;
        dv.z = base.z - pm.z;
        dv.w = base.w - pm.w;
        float pdot = dv.x * f.x + dv.y * f.y + dv.z * f.z + dv.w * f.w;
        float pn2  = dv.x * dv.x + dv.y * dv.y + dv.z * dv.z + dv.w * dv.w;
        #pragma unroll
        for (int o = 16; o > 0; o >>= 1) {
            pdot += __shfl_xor_sync(0xFFFFFFFFu, pdot, o);
            pn2  += __shfl_xor_sync(0xFFFFFFFFu, pn2,  o);
        }
        if (lane == s) { mydot = pdot; mydist2 = pn2; }
    }

    const float u = __ldg(unc);

    // Lanes 0..15: one softmax slot each. Others neutralized for the reduces.
    float a, logit;
    if (lane < 16) {
        int eidx;
        if (lane < 8) eidx = m_own * N_NODES + d_node;   // edge[mid0[s], dst]
        else          eidx = s_node * N_NODES + m_own;   // edge[src, mid1[s]]
        const float ev = __ldg(&edge[eidx]);
        logit = mydot + u * ev;
        a = 1.0f - sqrtf(mydist2);
    } else {
        logit = 0.f;
        a = -1e30f;
    }

    // max over the 16 valid lanes (others are -1e30)
    float mx = a;
    #pragma unroll
    for (int o = 16; o > 0; o >>= 1)
        mx = fmaxf(mx, __shfl_xor_sync(0xFFFFFFFFu, mx, o));

    const float e   = (lane < 16) ? __expf(a - mx) : 0.f;
    float num = logit * e;
    float den = e;
    #pragma unroll
    for (int o = 16; o > 0; o >>= 1) {
        num += __shfl_xor_sync(0xFFFFFFFFu, num, o);
        den += __shfl_xor_sync(0xFFFFFFFFu, den, o);
    }

    if (lane == 0) out[n] = num / den;
}

extern "C" void kernel_launch(void* const* d_in, const int* in_sizes, int n_in,
                              void* d_out, int out_size)
{
    const int*   src      = (const int*)  d_in[0];
    const int*   dst      = (const int*)  d_in[1];
    const int*   mid0     = (const int*)  d_in[2];
    const int*   mid1     = (const int*)  d_in[3];
    const float* position = (const float*)d_in[4];
    const float* src_f    = (const float*)d_in[5];
    const float* dst_f    = (const float*)d_in[6];
    const float* unc      = (const float*)d_in[7];
    const float* edge     = (const float*)d_in[8];
    float*       out      = (float*)      d_out;

    // 8 warps (8 queries) per 256-thread block
    const int blocks = NQUERY / 8;
    madgraph_kernel<<<blocks, 256>>>(src, dst, mid0, mid1, position,
                                     src_f, dst_f, unc, edge, out);
}

// round 5
// speedup vs baseline: 1.1111x; 1.0982x over previous
#include <cuda_runtime.h>
#include <cuda_bf16.h>

#define N_NODES 10000
#define DDIM    128
#define NQUERY  65536

__global__ __launch_bounds__(256)
void madgraph_kernel(const int* __restrict__ src,
                     const int* __restrict__ dst,
                     const int* __restrict__ mid0,
                     const int* __restrict__ mid1,
                     const float* __restrict__ position,
                     const float* __restrict__ src_field,
                     const float* __restrict__ dst_field,
                     const float* __restrict__ unc,
                     const float* __restrict__ edge,
                     float* __restrict__ out)
{
    const unsigned FULL = 0xFFFFFFFFu;
    const int warp = (blockIdx.x * blockDim.x + threadIdx.x) >> 5;
    const int lane = threadIdx.x & 31;
    if (warp >= NQUERY) return;
    const int n = warp;

    const int s_node = __ldg(&src[n]);
    const int d_node = __ldg(&dst[n]);

    const float4* pos4 = (const float4*)position;
    const float4* sf4  = (const float4*)src_field;
    const float4* df4  = (const float4*)dst_field;

    // Each lane owns float4 slice [lane*4 .. lane*4+3] of a 128-dim row.
    const float4 ps = __ldg(&pos4[s_node * 32 + lane]);
    const float4 pd = __ldg(&pos4[d_node * 32 + lane]);
    const float4 fd = __ldg(&df4 [d_node * 32 + lane]);
    const float4 fs = __ldg(&sf4 [s_node * 32 + lane]);

    // Lane l<8 holds mid0[n][l]; lanes 8..15 hold mid1[n][l-8].
    int m_own = 0;
    if (lane < 8)        m_own = __ldg(&mid0[n * 8 + lane]);
    else if (lane < 16)  m_own = __ldg(&mid1[n * 8 + (lane - 8)]);

    // Per-lane partials for all 16 samples: V[s]=dot_s, V[16+s]=n2_s.
    float V[32];

    #pragma unroll
    for (int s = 0; s < 16; ++s) {
        const int m = __shfl_sync(FULL, m_own, s);
        const float4 pm = __ldg(&pos4[m * 32 + lane]);
        const float4 base = (s < 8) ? ps : pd;
        const float4 f    = (s < 8) ? fd : fs;
        float dx = base.x - pm.x;
        float dy = base.y - pm.y;
        float dz = base.z - pm.z;
        float dw = base.w - pm.w;
        V[s]      = dx * f.x + dy * f.y + dz * f.z + dw * f.w;
        V[16 + s] = dx * dx  + dy * dy  + dz * dz  + dw * dw;
    }

    // Multi-value butterfly: 32 independent sums across 32 lanes in 31 shuffles.
    // After all stages, lane l holds the total for value-index l.
    #pragma unroll
    for (int m = 16, cnt = 32; m >= 1; m >>= 1, cnt >>= 1) {
        const int  half  = cnt >> 1;
        const bool upper = (lane & m) != 0;
        #pragma unroll
        for (int j = 0; j < 16; ++j) {          // bounded by max half
            if (j < half) {
                float send = upper ? V[j] : V[j + half];
                float recv = __shfl_xor_sync(FULL, send, m);
                V[j] = (upper ? V[j + half] : V[j]) + recv;
            }
        }
    }
    // lane s (<16): V[0] = dot_s ; lane s+16: V[0] = n2_s
    const float mate = __shfl_xor_sync(FULL, V[0], 16);   // lane s gets n2_s

    const float u = __ldg(unc);

    float a, logit;
    if (lane < 16) {
        int eidx;
        if (lane < 8) eidx = m_own * N_NODES + d_node;   // edge[mid0[s], dst]
        else          eidx = s_node * N_NODES + m_own;   // edge[src, mid1[s]]
        const float ev = __ldg(&edge[eidx]);
        logit = V[0] + u * ev;
        a = 1.0f - sqrtf(mate);
    } else {
        logit = 0.f;
        a = -1e30f;
    }

    // 16-wide softmax among lanes 0..15 (xor offsets < 16 stay within the half-warp)
    float mx = a;
    #pragma unroll
    for (int o = 8; o > 0; o >>= 1)
        mx = fmaxf(mx, __shfl_xor_sync(FULL, mx, o));

    const float e = (lane < 16) ? __expf(a - mx) : 0.f;
    float num = logit * e;
    float den = e;
    #pragma unroll
    for (int o = 8; o > 0; o >>= 1) {
        num += __shfl_xor_sync(FULL, num, o);
        den += __shfl_xor_sync(FULL, den, o);
    }

    if (lane == 0) out[n] = num / den;
}

extern "C" void kernel_launch(void* const* d_in, const int* in_sizes, int n_in,
                              void* d_out, int out_size)
{
    const int*   src      = (const int*)  d_in[0];
    const int*   dst      = (const int*)  d_in[1];
    const int*   mid0     = (const int*)  d_in[2];
    const int*   mid1     = (const int*)  d_in[3];
    const float* position = (const float*)d_in[4];
    const float* src_f    = (const float*)d_in[5];
    const float* dst_f    = (const float*)d_in[6];
    const float* unc      = (const float*)d_in[7];
    const float* edge     = (const float*)d_in[8];
    float*       out      = (float*)      d_out;

    const int blocks = NQUERY / 8;   // 8 warps (queries) per 256-thread block
    madgraph_kernel<<<blocks, 256>>>(src, dst, mid0, mid1, position,
                                     src_f, dst_f, unc, edge, out);
}

// round 6
// speedup vs baseline: 1.2457x; 1.1212x over previous
#include <cuda_runtime.h>
#include <cuda_bf16.h>

#define N_NODES 10000
#define DDIM    128
#define NQUERY  65536

// 16-value cross-warp butterfly sum: on entry each lane holds partials V[0..15];
// on exit lane l holds total of value index ((l>>1)&7) | ((l&16)>>1).
__device__ __forceinline__ float butterfly16(float* V, int lane)
{
    const unsigned FULL = 0xFFFFFFFFu;
    #pragma unroll
    for (int m = 16, cnt = 16; m >= 2; m >>= 1, cnt >>= 1) {
        const int  half  = cnt >> 1;
        const bool upper = (lane & m) != 0;
        #pragma unroll
        for (int j = 0; j < 8; ++j) {
            if (j < half) {
                float send = upper ? V[j] : V[j + half];
                float recv = __shfl_xor_sync(FULL, send, m);
                V[j] = (upper ? V[j + half] : V[j]) + recv;
            }
        }
    }
    return V[0] + __shfl_xor_sync(FULL, V[0], 1);
}

__global__ __launch_bounds__(256, 5)
void madgraph_kernel(const int* __restrict__ src,
                     const int* __restrict__ dst,
                     const int* __restrict__ mid0,
                     const int* __restrict__ mid1,
                     const float* __restrict__ position,
                     const float* __restrict__ src_field,
                     const float* __restrict__ dst_field,
                     const float* __restrict__ unc,
                     const float* __restrict__ edge,
                     float* __restrict__ out)
{
    const unsigned FULL = 0xFFFFFFFFu;
    const int warp = (blockIdx.x * blockDim.x + threadIdx.x) >> 5;
    const int lane = threadIdx.x & 31;
    if (warp >= NQUERY) return;
    const int n = warp;

    const int s_node = __ldg(&src[n]);
    const int d_node = __ldg(&dst[n]);

    // Lane l<8 holds mid0[n][l]; lanes 8..15 hold mid1[n][l-8].
    int m_own = 0;
    if (lane < 8)        m_own = __ldg(&mid0[n * 8 + lane]);
    else if (lane < 16)  m_own = __ldg(&mid1[n * 8 + (lane - 8)]);

    // Edge value for this lane's own sample — DRAM-resident table, issue ASAP.
    float ev_own = 0.f;
    if (lane < 16) {
        const int eidx = (lane < 8) ? (m_own * N_NODES + d_node)    // edge[mid0[s], dst]
                                    : (s_node * N_NODES + m_own);   // edge[src, mid1[s]]
        ev_own = __ldg(&edge[eidx]);
    }
    const float u = __ldg(unc);

    const float4* pos4 = (const float4*)position;
    const float4* sf4  = (const float4*)src_field;
    const float4* df4  = (const float4*)dst_field;

    float D1, D2;   // per-lane butterfly results (dot for lanes<16, n2 for lanes>=16)

    // ---- pass 1: samples 0..7  (base = pos[src], field = dst_field[dst]) ----
    {
        const float4 base = __ldg(&pos4[s_node * 32 + lane]);
        const float4 f    = __ldg(&df4 [d_node * 32 + lane]);
        int mm[8];
        #pragma unroll
        for (int s = 0; s < 8; ++s) mm[s] = __shfl_sync(FULL, m_own, s);
        float4 pm[8];
        #pragma unroll
        for (int s = 0; s < 8; ++s) pm[s] = __ldg(&pos4[mm[s] * 32 + lane]);
        float V[16];
        #pragma unroll
        for (int s = 0; s < 8; ++s) {
            float dx = base.x - pm[s].x, dy = base.y - pm[s].y;
            float dz = base.z - pm[s].z, dw = base.w - pm[s].w;
            V[s]     = dx * f.x + dy * f.y + dz * f.z + dw * f.w;
            V[8 + s] = dx * dx  + dy * dy  + dz * dz  + dw * dw;
        }
        D1 = butterfly16(V, lane);
    }

    // ---- pass 2: samples 8..15 (base = pos[dst], field = src_field[src]) ----
    {
        const float4 base = __ldg(&pos4[d_node * 32 + lane]);
        const float4 f    = __ldg(&sf4 [s_node * 32 + lane]);
        int mm[8];
        #pragma unroll
        for (int s = 0; s < 8; ++s) mm[s] = __shfl_sync(FULL, m_own, 8 + s);
        float4 pm[8];
        #pragma unroll
        for (int s = 0; s < 8; ++s) pm[s] = __ldg(&pos4[mm[s] * 32 + lane]);
        float V[16];
        #pragma unroll
        for (int s = 0; s < 8; ++s) {
            float dx = base.x - pm[s].x, dy = base.y - pm[s].y;
            float dz = base.z - pm[s].z, dw = base.w - pm[s].w;
            V[s]     = dx * f.x + dy * f.y + dz * f.z + dw * f.w;
            V[8 + s] = dx * dx  + dy * dy  + dz * dz  + dw * dw;
        }
        D2 = butterfly16(V, lane);
    }

    // Lanes 16..31 hold the squared norms; hand them to lanes 0..15.
    const float M1 = __shfl_xor_sync(FULL, D1, 16);
    const float M2 = __shfl_xor_sync(FULL, D2, 16);

    // Slot layout: lane l<16 — even lanes own pass-1 sample (l>>1),
    //                          odd  lanes own pass-2 sample 8+(l>>1).
    const int  odd  = lane & 1;
    const int  samp = (lane >> 1) | (odd ? 8 : 0);
    const float ev  = __shfl_sync(FULL, ev_own, samp);

    float a, logit;
    if (lane < 16) {
        const float dot = odd ? D2 : D1;
        const float n2  = odd ? M2 : M1;
        logit = dot + u * ev;
        a = 1.0f - sqrtf(n2);
    } else {
        logit = 0.f;
        a = -1e30f;
    }

    // 16-wide softmax among lanes 0..15 (xor offsets < 16 stay in the half-warp)
    float mx = a;
    #pragma unroll
    for (int o = 8; o > 0; o >>= 1)
        mx = fmaxf(mx, __shfl_xor_sync(FULL, mx, o));

    const float e = (lane < 16) ? __expf(a - mx) : 0.f;
    float num = logit * e;
    float den = e;
    #pragma unroll
    for (int o = 8; o > 0; o >>= 1) {
        num += __shfl_xor_sync(FULL, num, o);
        den += __shfl_xor_sync(FULL, den, o);
    }

    if (lane == 0) out[n] = num / den;
}

extern "C" void kernel_launch(void* const* d_in, const int* in_sizes, int n_in,
                              void* d_out, int out_size)
{
    const int*   src      = (const int*)  d_in[0];
    const int*   dst      = (const int*)  d_in[1];
    const int*   mid0     = (const int*)  d_in[2];
    const int*   mid1     = (const int*)  d_in[3];
    const float* position = (const float*)d_in[4];
    const float* src_f    = (const float*)d_in[5];
    const float* dst_f    = (const float*)d_in[6];
    const float* unc      = (const float*)d_in[7];
    const float* edge     = (const float*)d_in[8];
    float*       out      = (float*)      d_out;

    const int blocks = NQUERY / 8;   // 8 warps (queries) per 256-thread block
    madgraph_kernel<<<blocks, 256>>>(src, dst, mid0, mid1, position,
                                     src_f, dst_f, unc, edge, out);
}